// round 12
// baseline (speedup 1.0000x reference)
#include <cuda_runtime.h>
#include <cstdint>

#define D         64
#define EDGE_DIM  16
#define MSG_IN    144
#define UPD_IN    128
#define MAXN      50000
#define MAXE      800000
#define SCAN_B    1024

// ---------------- scratch (device globals; no allocation allowed) ----------------
__device__ __align__(256) float g_x[MAXN * D];
__device__ __align__(256) float g_P[MAXN * D];   // x @ W_i + msg_b  (dst side)
__device__ __align__(256) float g_Q[MAXN * D];   // x @ W_j          (src side)
__device__ __align__(256) float g_agg[MAXN * D];
__device__ __align__(256) float g_eas[(size_t)MAXE * EDGE_DIM];  // eattr, CSR order
__device__ int g_ssrc[MAXE];        // src, CSR order (grouped by dst)
__device__ int g_row[MAXN + 1];     // CSR row offsets per dst
__device__ int g_cnt[MAXN];
__device__ int g_incl[MAXN];
__device__ int g_pos[MAXN];
__device__ int g_bsum[64];
__device__ int g_bsumx[64];
__device__ int g_is64;

typedef unsigned long long u64;

// ---------------- packed f32x2 helpers ----------------
__device__ __forceinline__ u64 pack2(float lo, float hi) {
    u64 r; asm("mov.b64 %0, {%1,%2};" : "=l"(r) : "f"(lo), "f"(hi)); return r;
}
__device__ __forceinline__ void fma2(u64& acc, u64 a, u64 b) {
    asm("fma.rn.f32x2 %0, %1, %2, %0;" : "+l"(acc) : "l"(a), "l"(b));
}
__device__ __forceinline__ u64 add2(u64 a, u64 b) {
    u64 r; asm("add.rn.f32x2 %0, %1, %2;" : "=l"(r) : "l"(a), "l"(b)); return r;
}
__device__ __forceinline__ void unpack2(u64 v, float& lo, float& hi) {
    asm("mov.b64 {%0,%1}, %2;" : "=f"(lo), "=f"(hi) : "l"(v));
}

// ---------------- dtype sniffing ----------------
__global__ void detect_kernel(const unsigned int* __restrict__ idx) {
    __shared__ unsigned int acc[256];
    unsigned int v = 0;
    for (int i = threadIdx.x; i < 2048; i += 256) v |= idx[2 * i + 1];
    acc[threadIdx.x] = v;
    __syncthreads();
    for (int s = 128; s > 0; s >>= 1) {
        if (threadIdx.x < s) acc[threadIdx.x] |= acc[threadIdx.x + s];
        __syncthreads();
    }
    if (threadIdx.x == 0) g_is64 = (acc[0] == 0u) ? 1 : 0;
}

__global__ void zero_cnt_kernel(int N) {
    int i = blockIdx.x * 256 + threadIdx.x;
    if (i < N) g_cnt[i] = 0;
    if (blockIdx.x == 0 && threadIdx.x < 64) g_bsum[threadIdx.x] = 0;
}

__global__ void hist_kernel(const void* __restrict__ eidx, int E) {
    int i = blockIdx.x * 256 + threadIdx.x;
    if (i >= E) return;
    int dst;
    if (g_is64) dst = (int)reinterpret_cast<const long long*>(eidx)[(size_t)E + i];
    else        dst = reinterpret_cast<const int*>(eidx)[E + i];
    atomicAdd(&g_cnt[dst], 1);
}

__global__ void scan1_kernel(int N) {
    __shared__ int s[SCAN_B];
    int tid = threadIdx.x;
    int i = blockIdx.x * SCAN_B + tid;
    int v = (i < N) ? g_cnt[i] : 0;
    s[tid] = v;
    __syncthreads();
    for (int off = 1; off < SCAN_B; off <<= 1) {
        int t = (tid >= off) ? s[tid - off] : 0;
        __syncthreads();
        s[tid] += t;
        __syncthreads();
    }
    if (i < N) g_incl[i] = s[tid];
    if (tid == SCAN_B - 1) g_bsum[blockIdx.x] = s[tid];
}

__global__ void scan2_kernel(int nb) {
    __shared__ int s[64];
    int tid = threadIdx.x;
    s[tid] = (tid < nb) ? g_bsum[tid] : 0;
    __syncthreads();
    if (tid == 0) {
        int run = 0;
        for (int b = 0; b < nb; b++) { g_bsumx[b] = run; run += s[b]; }
    }
}

__global__ void scan3_kernel(int N, int E) {
    int i = blockIdx.x * 256 + threadIdx.x;
    if (i < N) {
        int start = g_incl[i] + g_bsumx[i / SCAN_B] - g_cnt[i];
        g_row[i] = start;
        g_pos[i] = start;
    }
    if (i == 0) g_row[N] = E;
}

// ---------------- scatter + fused eattr permute ----------------
// Sequential reads of eidx/eattr, random 64B-granule writes into CSR slots.
__global__ void scatter_kernel(const void* __restrict__ eidx,
                               const float* __restrict__ eattr, int E) {
    int i = blockIdx.x * 256 + threadIdx.x;
    if (i >= E) return;
    int src, dst;
    if (g_is64) {
        const long long* p = reinterpret_cast<const long long*>(eidx);
        src = (int)p[i];
        dst = (int)p[(size_t)E + i];
    } else {
        const int* p = reinterpret_cast<const int*>(eidx);
        src = p[i];
        dst = p[E + i];
    }
    int pos = atomicAdd(&g_pos[dst], 1);
    g_ssrc[pos] = src;
    const float4* ep = reinterpret_cast<const float4*>(eattr + (size_t)i * EDGE_DIM);
    float4 a = ep[0], b = ep[1], c = ep[2], d = ep[3];
    float4* op = reinterpret_cast<float4*>(g_eas + (size_t)pos * EDGE_DIM);
    op[0] = a; op[1] = b; op[2] = c; op[3] = d;
}

// ---------------- P/Q precompute: 2 nodes per thread ----------------
// 128 threads/block -> 256 nodes/block. Each LDS.128 of weights feeds 2 nodes.
__global__ void __launch_bounds__(128) pq_kernel(const float* __restrict__ xin,
                                                 const float* __restrict__ msg_w,
                                                 const float* __restrict__ msg_b,
                                                 int l, int N) {
    __shared__ __align__(16) float ws[64 * D];   // 16 KB
    __shared__ __align__(16) float bs[D];
    const int half = blockIdx.y;
    const float* x_src = xin ? xin : g_x;
    const float* W = msg_w + (size_t)l * MSG_IN * D + (size_t)half * 64 * D;
    for (int i = threadIdx.x; i < 64 * D; i += 128) ws[i] = W[i];
    if (threadIdx.x < D) bs[threadIdx.x] = half ? 0.f : msg_b[l * D + threadIdx.x];
    __syncthreads();

    const int v0 = (blockIdx.x * 128 + threadIdx.x) * 2;
    if (v0 >= N) return;
    const bool has1 = (v0 + 1 < N);

    u64 acc0[32], acc1[32];
    const u64* bp = reinterpret_cast<const u64*>(bs);
#pragma unroll
    for (int j = 0; j < 32; j++) { acc0[j] = bp[j]; acc1[j] = bp[j]; }

    const float4* xr0 = reinterpret_cast<const float4*>(x_src + (size_t)v0 * D);
    const float4* xr1 = reinterpret_cast<const float4*>(x_src + (size_t)(has1 ? v0 + 1 : v0) * D);

    for (int k4 = 0; k4 < 16; k4++) {
        float4 x0 = xr0[k4];
        float4 x1 = xr1[k4];
#pragma unroll
        for (int c = 0; c < 4; c++) {
            float s0 = (c == 0) ? x0.x : (c == 1) ? x0.y : (c == 2) ? x0.z : x0.w;
            float s1 = (c == 0) ? x1.x : (c == 1) ? x1.y : (c == 2) ? x1.z : x1.w;
            u64 a0 = pack2(s0, s0);
            u64 a1 = pack2(s1, s1);
            const ulonglong2* wr = reinterpret_cast<const ulonglong2*>(&ws[(k4 * 4 + c) * D]);
#pragma unroll
            for (int j4 = 0; j4 < 16; j4++) {
                ulonglong2 w = wr[j4];
                fma2(acc0[2 * j4],     a0, w.x);
                fma2(acc0[2 * j4 + 1], a0, w.y);
                fma2(acc1[2 * j4],     a1, w.x);
                fma2(acc1[2 * j4 + 1], a1, w.y);
            }
        }
    }
    float* base = (half ? g_Q : g_P);
    u64* o0 = reinterpret_cast<u64*>(base + (size_t)v0 * D);
#pragma unroll
    for (int j = 0; j < 32; j++) o0[j] = acc0[j];
    if (has1) {
        u64* o1 = reinterpret_cast<u64*>(base + (size_t)(v0 + 1) * D);
#pragma unroll
        for (int j = 0; j < 32; j++) o1[j] = acc1[j];
    }
}

// ---------------- edge message helper (no shfl: ea via uniform loads) ----------------
__device__ __forceinline__ u64 msg16(u64 pv, u64 q, float4 A, float4 B, float4 C, float4 Dv,
                                     const u64* Wreg) {
    u64 m0 = add2(pv, q);
    u64 m1 = 0ULL;
    fma2(m0, pack2(A.x, A.x), Wreg[0]);  fma2(m1, pack2(A.y, A.y), Wreg[1]);
    fma2(m0, pack2(A.z, A.z), Wreg[2]);  fma2(m1, pack2(A.w, A.w), Wreg[3]);
    fma2(m0, pack2(B.x, B.x), Wreg[4]);  fma2(m1, pack2(B.y, B.y), Wreg[5]);
    fma2(m0, pack2(B.z, B.z), Wreg[6]);  fma2(m1, pack2(B.w, B.w), Wreg[7]);
    fma2(m0, pack2(C.x, C.x), Wreg[8]);  fma2(m1, pack2(C.y, C.y), Wreg[9]);
    fma2(m0, pack2(C.z, C.z), Wreg[10]); fma2(m1, pack2(C.w, C.w), Wreg[11]);
    fma2(m0, pack2(Dv.x, Dv.x), Wreg[12]); fma2(m1, pack2(Dv.y, Dv.y), Wreg[13]);
    fma2(m0, pack2(Dv.z, Dv.z), Wreg[14]); fma2(m1, pack2(Dv.w, Dv.w), Wreg[15]);
    m0 = add2(m0, m1);
    float lo, hi; unpack2(m0, lo, hi);
    return pack2(fmaxf(lo, 0.f), fmaxf(hi, 0.f));
}

// ---------------- edge pass: CSR warp-per-node, 2-edge batches, no atomics ----------------
__global__ void __launch_bounds__(256) edge_kernel(const float* __restrict__ msg_w,
                                                   int l, int N) {
    const float* W = msg_w + (size_t)l * MSG_IN * D + (size_t)128 * D;
    const int lane = threadIdx.x & 31;
    const int v = (blockIdx.x * 256 + threadIdx.x) >> 5;

    u64 Wreg[16];
#pragma unroll
    for (int k = 0; k < 16; k++)
        Wreg[k] = *reinterpret_cast<const u64*>(W + k * D + 2 * lane);

    if (v >= N) return;
    const int e0 = g_row[v];
    const int e1 = g_row[v + 1];

    u64 accv = 0ULL;
    if (e0 < e1) {
        const u64 pv = *reinterpret_cast<const u64*>(g_P + (size_t)v * D + 2 * lane);
        int e = e0;
        for (; e + 2 <= e1; e += 2) {
            const int s0 = g_ssrc[e];
            const int s1 = g_ssrc[e + 1];
            const u64 q0 = *reinterpret_cast<const u64*>(g_Q + (size_t)s0 * D + 2 * lane);
            const u64 q1 = *reinterpret_cast<const u64*>(g_Q + (size_t)s1 * D + 2 * lane);
            const float4* ep0 = reinterpret_cast<const float4*>(g_eas + (size_t)e * EDGE_DIM);
            const float4* ep1 = reinterpret_cast<const float4*>(g_eas + (size_t)(e + 1) * EDGE_DIM);
            float4 a0 = ep0[0], b0 = ep0[1], c0 = ep0[2], d0 = ep0[3];
            float4 a1 = ep1[0], b1 = ep1[1], c1 = ep1[2], d1 = ep1[3];
            accv = add2(accv, msg16(pv, q0, a0, b0, c0, d0, Wreg));
            accv = add2(accv, msg16(pv, q1, a1, b1, c1, d1, Wreg));
        }
        if (e < e1) {
            const int s0 = g_ssrc[e];
            const u64 q0 = *reinterpret_cast<const u64*>(g_Q + (size_t)s0 * D + 2 * lane);
            const float4* ep0 = reinterpret_cast<const float4*>(g_eas + (size_t)e * EDGE_DIM);
            accv = add2(accv, msg16(pv, q0, ep0[0], ep0[1], ep0[2], ep0[3], Wreg));
        }
    }
    *reinterpret_cast<u64*>(g_agg + (size_t)v * D + 2 * lane) = accv;
}

// ---------------- node update: 2 nodes per thread ----------------
__global__ void __launch_bounds__(128) upd_kernel(const float* __restrict__ xin,
                                                  const float* __restrict__ upd_w,
                                                  const float* __restrict__ upd_b,
                                                  int l, int N, float* __restrict__ xout) {
    __shared__ __align__(16) float ws[UPD_IN * D];   // 32 KB
    __shared__ __align__(16) float bs[D];
    const float* x_src = xin ? xin : g_x;
    float* x_dst = xout ? xout : g_x;
    const float* W = upd_w + (size_t)l * UPD_IN * D;
    for (int i = threadIdx.x; i < UPD_IN * D; i += 128) ws[i] = W[i];
    if (threadIdx.x < D) bs[threadIdx.x] = upd_b[l * D + threadIdx.x];
    __syncthreads();

    const int v0 = (blockIdx.x * 128 + threadIdx.x) * 2;
    if (v0 >= N) return;
    const bool has1 = (v0 + 1 < N);
    const int v1 = has1 ? v0 + 1 : v0;

    u64 acc0[32], acc1[32];
    const u64* bp = reinterpret_cast<const u64*>(bs);
#pragma unroll
    for (int j = 0; j < 32; j++) { acc0[j] = bp[j]; acc1[j] = bp[j]; }

    const float4* xr0 = reinterpret_cast<const float4*>(x_src + (size_t)v0 * D);
    const float4* xr1 = reinterpret_cast<const float4*>(x_src + (size_t)v1 * D);
    const float4* ar0 = reinterpret_cast<const float4*>(g_agg + (size_t)v0 * D);
    const float4* ar1 = reinterpret_cast<const float4*>(g_agg + (size_t)v1 * D);

    for (int k4 = 0; k4 < 16; k4++) {
        float4 x0 = xr0[k4];
        float4 x1 = xr1[k4];
#pragma unroll
        for (int c = 0; c < 4; c++) {
            float s0 = (c == 0) ? x0.x : (c == 1) ? x0.y : (c == 2) ? x0.z : x0.w;
            float s1 = (c == 0) ? x1.x : (c == 1) ? x1.y : (c == 2) ? x1.z : x1.w;
            u64 a0 = pack2(s0, s0);
            u64 a1 = pack2(s1, s1);
            const ulonglong2* wr = reinterpret_cast<const ulonglong2*>(&ws[(k4 * 4 + c) * D]);
#pragma unroll
            for (int j4 = 0; j4 < 16; j4++) {
                ulonglong2 w = wr[j4];
                fma2(acc0[2 * j4],     a0, w.x);
                fma2(acc0[2 * j4 + 1], a0, w.y);
                fma2(acc1[2 * j4],     a1, w.x);
                fma2(acc1[2 * j4 + 1], a1, w.y);
            }
        }
    }
    for (int k4 = 0; k4 < 16; k4++) {
        float4 x0 = ar0[k4];
        float4 x1 = ar1[k4];
#pragma unroll
        for (int c = 0; c < 4; c++) {
            float s0 = (c == 0) ? x0.x : (c == 1) ? x0.y : (c == 2) ? x0.z : x0.w;
            float s1 = (c == 0) ? x1.x : (c == 1) ? x1.y : (c == 2) ? x1.z : x1.w;
            u64 a0 = pack2(s0, s0);
            u64 a1 = pack2(s1, s1);
            const ulonglong2* wr = reinterpret_cast<const ulonglong2*>(&ws[(64 + k4 * 4 + c) * D]);
#pragma unroll
            for (int j4 = 0; j4 < 16; j4++) {
                ulonglong2 w = wr[j4];
                fma2(acc0[2 * j4],     a0, w.x);
                fma2(acc0[2 * j4 + 1], a0, w.y);
                fma2(acc1[2 * j4],     a1, w.x);
                fma2(acc1[2 * j4 + 1], a1, w.y);
            }
        }
    }

    float* o0 = x_dst + (size_t)v0 * D;
#pragma unroll
    for (int j = 0; j < 32; j++) {
        float lo, hi; unpack2(acc0[j], lo, hi);
        float2 rv; rv.x = fmaxf(lo, 0.f); rv.y = fmaxf(hi, 0.f);
        *reinterpret_cast<float2*>(&o0[2 * j]) = rv;
    }
    if (has1) {
        float* o1 = x_dst + (size_t)(v0 + 1) * D;
#pragma unroll
        for (int j = 0; j < 32; j++) {
            float lo, hi; unpack2(acc1[j], lo, hi);
            float2 rv; rv.x = fmaxf(lo, 0.f); rv.y = fmaxf(hi, 0.f);
            *reinterpret_cast<float2*>(&o1[2 * j]) = rv;
        }
    }
}

// ---------------- launcher ----------------
extern "C" void kernel_launch(void* const* d_in, const int* in_sizes, int n_in,
                              void* d_out, int out_size) {
    const float* x      = (const float*)d_in[0];
    const void*  eidx   = d_in[1];
    const float* eattr  = (const float*)d_in[2];
    const float* msg_w  = (const float*)d_in[3];
    const float* msg_b  = (const float*)d_in[4];
    const float* upd_w  = (const float*)d_in[5];
    const float* upd_b  = (const float*)d_in[6];

    const int N = in_sizes[0] / D;
    const int E = in_sizes[2] / EDGE_DIM;
    const int L = in_sizes[4] / D;

    const int nB = (N + 255) / 256;
    const int eB = (E + 255) / 256;
    const int scanB = (N + SCAN_B - 1) / SCAN_B;

    // ---- preprocessing: CSR by dst with fused eattr permute ----
    detect_kernel<<<1, 256>>>((const unsigned int*)eidx);
    zero_cnt_kernel<<<nB, 256>>>(N);
    hist_kernel<<<eB, 256>>>(eidx, E);
    scan1_kernel<<<scanB, SCAN_B>>>(N);
    scan2_kernel<<<1, 64>>>(scanB);
    scan3_kernel<<<nB, 256>>>(N, E);
    scatter_kernel<<<eB, 256>>>(eidx, eattr, E);

    const int node2_blocks = (N + 255) / 256;   // 128 thr, 2 nodes/thread
    const int edge_blocks = (N + 7) / 8;        // 8 warps/block, warp per node

    for (int l = 0; l < L; l++) {
        const float* xin = (l == 0) ? x : nullptr;            // nullptr -> g_x
        float* xout = (l == L - 1) ? (float*)d_out : nullptr; // nullptr -> g_x

        dim3 pq_grid(node2_blocks, 2);
        pq_kernel<<<pq_grid, 128>>>(xin, msg_w, msg_b, l, N);
        edge_kernel<<<edge_blocks, 256>>>(msg_w, l, N);
        upd_kernel<<<node2_blocks, 128>>>(xin, upd_w, upd_b, l, N, xout);
    }
}

// round 13
// speedup vs baseline: 1.0771x; 1.0771x over previous
#include <cuda_runtime.h>
#include <cstdint>

#define D         64
#define EDGE_DIM  16
#define MSG_IN    144
#define UPD_IN    128
#define MAXN      50000
#define MAXE      800000

// ---------------- scratch (device globals; no allocation allowed) ----------------
__device__ __align__(256) float g_x[MAXN * D];
__device__ __align__(256) float g_P[MAXN * D];   // x @ W_i + msg_b  (dst side)
__device__ __align__(256) float g_Q[MAXN * D];   // x @ W_j          (src side)
__device__ __align__(256) float g_agg[MAXN * D];
__device__ int g_src[MAXE];
__device__ int g_dst[MAXE];
__device__ int g_is64;

typedef unsigned long long u64;

// ---------------- packed f32x2 helpers ----------------
__device__ __forceinline__ u64 pack2(float lo, float hi) {
    u64 r; asm("mov.b64 %0, {%1,%2};" : "=l"(r) : "f"(lo), "f"(hi)); return r;
}
__device__ __forceinline__ void fma2(u64& acc, u64 a, u64 b) {
    asm("fma.rn.f32x2 %0, %1, %2, %0;" : "+l"(acc) : "l"(a), "l"(b));
}
__device__ __forceinline__ u64 add2(u64 a, u64 b) {
    u64 r; asm("add.rn.f32x2 %0, %1, %2;" : "=l"(r) : "l"(a), "l"(b)); return r;
}
__device__ __forceinline__ void unpack2(u64 v, float& lo, float& hi) {
    asm("mov.b64 {%0,%1}, %2;" : "=f"(lo), "=f"(hi) : "l"(v));
}

// ---------------- dtype sniffing for edge_index ----------------
__global__ void detect_kernel(const unsigned int* __restrict__ idx) {
    __shared__ unsigned int acc[256];
    unsigned int v = 0;
    for (int i = threadIdx.x; i < 2048; i += 256) v |= idx[2 * i + 1];
    acc[threadIdx.x] = v;
    __syncthreads();
    for (int s = 128; s > 0; s >>= 1) {
        if (threadIdx.x < s) acc[threadIdx.x] |= acc[threadIdx.x + s];
        __syncthreads();
    }
    if (threadIdx.x == 0) g_is64 = (acc[0] == 0u) ? 1 : 0;
}

// ---------------- convert edge_index to int32 src/dst arrays ----------------
__global__ void conv_idx_kernel(const void* __restrict__ eidx, int E) {
    int i = blockIdx.x * 256 + threadIdx.x;
    if (i >= E) return;
    if (g_is64) {
        const long long* p = reinterpret_cast<const long long*>(eidx);
        g_src[i] = (int)p[i];
        g_dst[i] = (int)p[(size_t)E + i];
    } else {
        const int* p = reinterpret_cast<const int*>(eidx);
        g_src[i] = p[i];
        g_dst[i] = p[E + i];
    }
}

// ---------------- P/Q precompute: persistent blocks, 1 thread/node, zeroes agg ----------------
// grid (148, 2): blockIdx.y==0 -> P (+bias, zero agg), 1 -> Q. Stride loop over nodes.
__global__ void __launch_bounds__(256) pq_kernel(const float* __restrict__ xin,
                                                 const float* __restrict__ msg_w,
                                                 const float* __restrict__ msg_b,
                                                 int l, int N) {
    __shared__ __align__(16) float ws[64 * D];   // 16 KB
    __shared__ __align__(16) float bs[D];
    const int half = blockIdx.y;
    const float* x_src = xin ? xin : g_x;
    const float* W = msg_w + (size_t)l * MSG_IN * D + (size_t)half * 64 * D;
    for (int i = threadIdx.x; i < 64 * D; i += 256) ws[i] = W[i];
    if (threadIdx.x < D) bs[threadIdx.x] = half ? 0.f : msg_b[l * D + threadIdx.x];
    __syncthreads();

    const int stride = gridDim.x * 256;
    for (int v = blockIdx.x * 256 + threadIdx.x; v < N; v += stride) {
        if (half == 0) {   // zero agg row for this layer (edge kernel follows in-stream)
            float4 z = make_float4(0.f, 0.f, 0.f, 0.f);
            float4* ap = reinterpret_cast<float4*>(g_agg + (size_t)v * D);
#pragma unroll
            for (int j = 0; j < 16; j++) ap[j] = z;
        }

        u64 acc[32];
        const u64* bp = reinterpret_cast<const u64*>(bs);
#pragma unroll
        for (int j = 0; j < 32; j++) acc[j] = bp[j];

        const float4* xr = reinterpret_cast<const float4*>(x_src + (size_t)v * D);
        for (int k4 = 0; k4 < 16; k4++) {
            float4 xv = xr[k4];
#pragma unroll
            for (int c = 0; c < 4; c++) {
                float xs = (c == 0) ? xv.x : (c == 1) ? xv.y : (c == 2) ? xv.z : xv.w;
                u64 a = pack2(xs, xs);
                const ulonglong2* wr = reinterpret_cast<const ulonglong2*>(&ws[(k4 * 4 + c) * D]);
#pragma unroll
                for (int j4 = 0; j4 < 16; j4++) {
                    ulonglong2 w = wr[j4];
                    fma2(acc[2 * j4],     a, w.x);
                    fma2(acc[2 * j4 + 1], a, w.y);
                }
            }
        }
        float* out = (half ? g_Q : g_P) + (size_t)v * D;
        u64* o64 = reinterpret_cast<u64*>(out);
#pragma unroll
        for (int j = 0; j < 32; j++) o64[j] = acc[j];
    }
}

// ---------------- edge pass: warp-per-edge, W_e in registers, shfl-broadcast eattr ----------------
// agg[dst] += relu(P[dst] + Q[src] + ea @ W_e). Lane owns cols (2*lane, 2*lane+1).
#define EPW 16  // edges per warp
__global__ void __launch_bounds__(256) edge_kernel(const float* __restrict__ eattr,
                                                   const float* __restrict__ msg_w,
                                                   int l, int E) {
    const float* W = msg_w + (size_t)l * MSG_IN * D + (size_t)128 * D;
    const int lane = threadIdx.x & 31;
    const int gwarp = (blockIdx.x * 256 + threadIdx.x) >> 5;

    // W_e column pair for this lane: 16 u64 registers, loaded once per warp.
    u64 Wreg[16];
#pragma unroll
    for (int k = 0; k < 16; k++)
        Wreg[k] = *reinterpret_cast<const u64*>(W + k * D + 2 * lane);

    const int e0 = gwarp * EPW;
#pragma unroll 2
    for (int i = 0; i < EPW; i++) {
        const int e = e0 + i;
        if (e < E) {
            const int src = g_src[e];
            const int dst = g_dst[e];
            float myea = 0.f;
            if (lane < EDGE_DIM) myea = eattr[(size_t)e * EDGE_DIM + lane];

            const u64 p = *reinterpret_cast<const u64*>(g_P + (size_t)dst * D + 2 * lane);
            const u64 q = *reinterpret_cast<const u64*>(g_Q + (size_t)src * D + 2 * lane);

            u64 acc0 = add2(p, q);
            u64 acc1 = 0ULL;
#pragma unroll
            for (int k = 0; k < EDGE_DIM; k += 2) {
                float s0 = __shfl_sync(0xffffffffu, myea, k);
                float s1 = __shfl_sync(0xffffffffu, myea, k + 1);
                fma2(acc0, pack2(s0, s0), Wreg[k]);
                fma2(acc1, pack2(s1, s1), Wreg[k + 1]);
            }
            acc0 = add2(acc0, acc1);

            float lo, hi;
            unpack2(acc0, lo, hi);
            lo = fmaxf(lo, 0.f);
            hi = fmaxf(hi, 0.f);
            asm volatile("red.global.add.v2.f32 [%0], {%1,%2};"
                         :: "l"(g_agg + (size_t)dst * D + 2 * lane), "f"(lo), "f"(hi)
                         : "memory");
        }
    }
}

// ---------------- node update: persistent blocks, 1 thread/node ----------------
__global__ void __launch_bounds__(256) upd_kernel(const float* __restrict__ xin,
                                                  const float* __restrict__ upd_w,
                                                  const float* __restrict__ upd_b,
                                                  int l, int N, float* __restrict__ xout) {
    __shared__ __align__(16) float ws[UPD_IN * D];   // 32 KB
    __shared__ __align__(16) float bs[D];
    const float* x_src = xin ? xin : g_x;
    float* x_dst = xout ? xout : g_x;
    const float* W = upd_w + (size_t)l * UPD_IN * D;
    for (int i = threadIdx.x; i < UPD_IN * D; i += 256) ws[i] = W[i];
    if (threadIdx.x < D) bs[threadIdx.x] = upd_b[l * D + threadIdx.x];
    __syncthreads();

    const int stride = gridDim.x * 256;
    for (int v = blockIdx.x * 256 + threadIdx.x; v < N; v += stride) {
        u64 acc[32];
        const u64* bp = reinterpret_cast<const u64*>(bs);
#pragma unroll
        for (int j = 0; j < 32; j++) acc[j] = bp[j];

        const float4* xr = reinterpret_cast<const float4*>(x_src + (size_t)v * D);
        const float4* ar = reinterpret_cast<const float4*>(g_agg + (size_t)v * D);

        for (int k4 = 0; k4 < 16; k4++) {
            float4 xv = xr[k4];
#pragma unroll
            for (int c = 0; c < 4; c++) {
                float xs = (c == 0) ? xv.x : (c == 1) ? xv.y : (c == 2) ? xv.z : xv.w;
                u64 a = pack2(xs, xs);
                const ulonglong2* wr = reinterpret_cast<const ulonglong2*>(&ws[(k4 * 4 + c) * D]);
#pragma unroll
                for (int j4 = 0; j4 < 16; j4++) {
                    ulonglong2 w = wr[j4];
                    fma2(acc[2 * j4],     a, w.x);
                    fma2(acc[2 * j4 + 1], a, w.y);
                }
            }
        }
        for (int k4 = 0; k4 < 16; k4++) {
            float4 av = ar[k4];
#pragma unroll
            for (int c = 0; c < 4; c++) {
                float xs = (c == 0) ? av.x : (c == 1) ? av.y : (c == 2) ? av.z : av.w;
                u64 a = pack2(xs, xs);
                const ulonglong2* wr = reinterpret_cast<const ulonglong2*>(&ws[(64 + k4 * 4 + c) * D]);
#pragma unroll
                for (int j4 = 0; j4 < 16; j4++) {
                    ulonglong2 w = wr[j4];
                    fma2(acc[2 * j4],     a, w.x);
                    fma2(acc[2 * j4 + 1], a, w.y);
                }
            }
        }

        float* o = x_dst + (size_t)v * D;
#pragma unroll
        for (int j = 0; j < 32; j++) {
            float lo, hi;
            unpack2(acc[j], lo, hi);
            float2 rv;
            rv.x = fmaxf(lo, 0.f);
            rv.y = fmaxf(hi, 0.f);
            *reinterpret_cast<float2*>(&o[2 * j]) = rv;
        }
    }
}

// ---------------- launcher ----------------
extern "C" void kernel_launch(void* const* d_in, const int* in_sizes, int n_in,
                              void* d_out, int out_size) {
    const float* x      = (const float*)d_in[0];
    const void*  eidx   = d_in[1];
    const float* eattr  = (const float*)d_in[2];
    const float* msg_w  = (const float*)d_in[3];
    const float* msg_b  = (const float*)d_in[4];
    const float* upd_w  = (const float*)d_in[5];
    const float* upd_b  = (const float*)d_in[6];

    const int N = in_sizes[0] / D;
    const int E = in_sizes[2] / EDGE_DIM;
    const int L = in_sizes[4] / D;

    detect_kernel<<<1, 256>>>((const unsigned int*)eidx);
    conv_idx_kernel<<<(E + 255) / 256, 256>>>(eidx, E);

    // Persistent node grids: one balanced wave over 148 SMs.
    int pers = (N + 255) / 256;
    if (pers > 148) pers = 148;
    const int edge_blocks = (E + 8 * EPW - 1) / (8 * EPW);

    for (int l = 0; l < L; l++) {
        const float* xin = (l == 0) ? x : nullptr;            // nullptr -> g_x
        float* xout = (l == L - 1) ? (float*)d_out : nullptr; // nullptr -> g_x

        dim3 pq_grid(pers, 2);
        pq_kernel<<<pq_grid, 256>>>(xin, msg_w, msg_b, l, N);
        edge_kernel<<<edge_blocks, 256>>>(eattr, msg_w, l, E);
        upd_kernel<<<pers, 256>>>(xin, upd_w, upd_b, l, N, xout);
    }
}

// round 14
// speedup vs baseline: 1.1494x; 1.0671x over previous
#include <cuda_runtime.h>
#include <cstdint>

#define D         64
#define EDGE_DIM  16
#define MSG_IN    144
#define UPD_IN    128
#define MAXN      50000
#define MAXE      800000

// ---------------- scratch (device globals; no allocation allowed) ----------------
__device__ __align__(256) float g_x[MAXN * D];
__device__ __align__(256) float g_P[MAXN * D];   // x @ W_i + msg_b  (dst side)
__device__ __align__(256) float g_Q[MAXN * D];   // x @ W_j          (src side)
__device__ __align__(256) float g_agg[MAXN * D];
__device__ int g_src[MAXE];
__device__ int g_dst[MAXE];
__device__ int g_is64;

typedef unsigned long long u64;

// ---------------- packed f32x2 helpers ----------------
__device__ __forceinline__ u64 pack2(float lo, float hi) {
    u64 r; asm("mov.b64 %0, {%1,%2};" : "=l"(r) : "f"(lo), "f"(hi)); return r;
}
__device__ __forceinline__ void fma2(u64& acc, u64 a, u64 b) {
    asm("fma.rn.f32x2 %0, %1, %2, %0;" : "+l"(acc) : "l"(a), "l"(b));
}
__device__ __forceinline__ u64 add2(u64 a, u64 b) {
    u64 r; asm("add.rn.f32x2 %0, %1, %2;" : "=l"(r) : "l"(a), "l"(b)); return r;
}
__device__ __forceinline__ void unpack2(u64 v, float& lo, float& hi) {
    asm("mov.b64 {%0,%1}, %2;" : "=f"(lo), "=f"(hi) : "l"(v));
}

// ---------------- dtype sniffing for edge_index ----------------
__global__ void detect_kernel(const unsigned int* __restrict__ idx) {
    __shared__ unsigned int acc[256];
    unsigned int v = 0;
    for (int i = threadIdx.x; i < 2048; i += 256) v |= idx[2 * i + 1];
    acc[threadIdx.x] = v;
    __syncthreads();
    for (int s = 128; s > 0; s >>= 1) {
        if (threadIdx.x < s) acc[threadIdx.x] |= acc[threadIdx.x + s];
        __syncthreads();
    }
    if (threadIdx.x == 0) g_is64 = (acc[0] == 0u) ? 1 : 0;
}

// ---------------- convert edge_index to int32 src/dst arrays ----------------
__global__ void conv_idx_kernel(const void* __restrict__ eidx, int E) {
    int i = blockIdx.x * 256 + threadIdx.x;
    if (i >= E) return;
    if (g_is64) {
        const long long* p = reinterpret_cast<const long long*>(eidx);
        g_src[i] = (int)p[i];
        g_dst[i] = (int)p[(size_t)E + i];
    } else {
        const int* p = reinterpret_cast<const int*>(eidx);
        g_src[i] = p[i];
        g_dst[i] = p[E + i];
    }
}

// ---------------- P/Q precompute: persistent blocks, 1 thread/node, zeroes agg ----------------
__global__ void __launch_bounds__(256) pq_kernel(const float* __restrict__ xin,
                                                 const float* __restrict__ msg_w,
                                                 const float* __restrict__ msg_b,
                                                 int l, int N) {
    __shared__ __align__(16) float ws[64 * D];   // 16 KB
    __shared__ __align__(16) float bs[D];
    const int half = blockIdx.y;
    const float* x_src = xin ? xin : g_x;
    const float* W = msg_w + (size_t)l * MSG_IN * D + (size_t)half * 64 * D;
    for (int i = threadIdx.x; i < 64 * D; i += 256) ws[i] = W[i];
    if (threadIdx.x < D) bs[threadIdx.x] = half ? 0.f : msg_b[l * D + threadIdx.x];
    __syncthreads();

    const int stride = gridDim.x * 256;
    for (int v = blockIdx.x * 256 + threadIdx.x; v < N; v += stride) {
        if (half == 0) {   // zero agg row for this layer (edge kernel follows in-stream)
            float4 z = make_float4(0.f, 0.f, 0.f, 0.f);
            float4* ap = reinterpret_cast<float4*>(g_agg + (size_t)v * D);
#pragma unroll
            for (int j = 0; j < 16; j++) ap[j] = z;
        }

        u64 acc[32];
        const u64* bp = reinterpret_cast<const u64*>(bs);
#pragma unroll
        for (int j = 0; j < 32; j++) acc[j] = bp[j];

        const float4* xr = reinterpret_cast<const float4*>(x_src + (size_t)v * D);
        for (int k4 = 0; k4 < 16; k4++) {
            float4 xv = xr[k4];
#pragma unroll
            for (int c = 0; c < 4; c++) {
                float xs = (c == 0) ? xv.x : (c == 1) ? xv.y : (c == 2) ? xv.z : xv.w;
                u64 a = pack2(xs, xs);
                const ulonglong2* wr = reinterpret_cast<const ulonglong2*>(&ws[(k4 * 4 + c) * D]);
#pragma unroll
                for (int j4 = 0; j4 < 16; j4++) {
                    ulonglong2 w = wr[j4];
                    fma2(acc[2 * j4],     a, w.x);
                    fma2(acc[2 * j4 + 1], a, w.y);
                }
            }
        }
        float* out = (half ? g_Q : g_P) + (size_t)v * D;
        u64* o64 = reinterpret_cast<u64*>(out);
#pragma unroll
        for (int j = 0; j < 32; j++) o64[j] = acc[j];
    }
}

// ---------------- edge pass: warp-per-edge, software-pipelined gathers ----------------
// agg[dst] += relu(P[dst] + Q[src] + ea @ W_e). Lane owns cols (2*lane, 2*lane+1).
// Next edge's P/Q/eattr loads are issued BEFORE the current edge's compute+red,
// and the red carries no memory clobber so the compiler keeps them hoisted.
#define EPW 16  // edges per warp
__global__ void __launch_bounds__(256) edge_kernel(const float* __restrict__ eattr,
                                                   const float* __restrict__ msg_w,
                                                   int l, int E) {
    const float* W = msg_w + (size_t)l * MSG_IN * D + (size_t)128 * D;
    const int lane = threadIdx.x & 31;
    const int gwarp = (blockIdx.x * 256 + threadIdx.x) >> 5;

    u64 Wreg[16];
#pragma unroll
    for (int k = 0; k < 16; k++)
        Wreg[k] = *reinterpret_cast<const u64*>(W + k * D + 2 * lane);

    const int e0 = gwarp * EPW;
    if (e0 >= E) return;
    const int eend = (e0 + EPW < E) ? e0 + EPW : E;

    // prologue: load first edge
    int dst = g_dst[e0];
    u64 p = *reinterpret_cast<const u64*>(g_P + (size_t)dst * D + 2 * lane);
    u64 q = *reinterpret_cast<const u64*>(g_Q + (size_t)g_src[e0] * D + 2 * lane);
    float myea = (lane < EDGE_DIM) ? eattr[(size_t)e0 * EDGE_DIM + lane] : 0.f;

    for (int e = e0; e < eend; e++) {
        // prefetch next edge (loads in flight during current compute)
        int ndst = 0;
        u64 np = 0ULL, nq = 0ULL;
        float nea = 0.f;
        if (e + 1 < eend) {
            ndst = g_dst[e + 1];
            np = *reinterpret_cast<const u64*>(g_P + (size_t)ndst * D + 2 * lane);
            nq = *reinterpret_cast<const u64*>(g_Q + (size_t)g_src[e + 1] * D + 2 * lane);
            nea = (lane < EDGE_DIM) ? eattr[(size_t)(e + 1) * EDGE_DIM + lane] : 0.f;
        }

        // compute current edge
        u64 acc0 = add2(p, q);
        u64 acc1 = 0ULL;
#pragma unroll
        for (int k = 0; k < EDGE_DIM; k += 2) {
            float s0 = __shfl_sync(0xffffffffu, myea, k);
            float s1 = __shfl_sync(0xffffffffu, myea, k + 1);
            fma2(acc0, pack2(s0, s0), Wreg[k]);
            fma2(acc1, pack2(s1, s1), Wreg[k + 1]);
        }
        acc0 = add2(acc0, acc1);

        float lo, hi;
        unpack2(acc0, lo, hi);
        lo = fmaxf(lo, 0.f);
        hi = fmaxf(hi, 0.f);
        // no "memory" clobber: allows next iteration's loads to stay hoisted above
        asm volatile("red.global.add.v2.f32 [%0], {%1,%2};"
                     :: "l"(g_agg + (size_t)dst * D + 2 * lane), "f"(lo), "f"(hi));

        dst = ndst; p = np; q = nq; myea = nea;
    }
}

// ---------------- node update: persistent blocks, 1 thread/node ----------------
__global__ void __launch_bounds__(256) upd_kernel(const float* __restrict__ xin,
                                                  const float* __restrict__ upd_w,
                                                  const float* __restrict__ upd_b,
                                                  int l, int N, float* __restrict__ xout) {
    __shared__ __align__(16) float ws[UPD_IN * D];   // 32 KB
    __shared__ __align__(16) float bs[D];
    const float* x_src = xin ? xin : g_x;
    float* x_dst = xout ? xout : g_x;
    const float* W = upd_w + (size_t)l * UPD_IN * D;
    for (int i = threadIdx.x; i < UPD_IN * D; i += 256) ws[i] = W[i];
    if (threadIdx.x < D) bs[threadIdx.x] = upd_b[l * D + threadIdx.x];
    __syncthreads();

    const int stride = gridDim.x * 256;
    for (int v = blockIdx.x * 256 + threadIdx.x; v < N; v += stride) {
        u64 acc[32];
        const u64* bp = reinterpret_cast<const u64*>(bs);
#pragma unroll
        for (int j = 0; j < 32; j++) acc[j] = bp[j];

        const float4* xr = reinterpret_cast<const float4*>(x_src + (size_t)v * D);
        const float4* ar = reinterpret_cast<const float4*>(g_agg + (size_t)v * D);

        for (int k4 = 0; k4 < 16; k4++) {
            float4 xv = xr[k4];
#pragma unroll
            for (int c = 0; c < 4; c++) {
                float xs = (c == 0) ? xv.x : (c == 1) ? xv.y : (c == 2) ? xv.z : xv.w;
                u64 a = pack2(xs, xs);
                const ulonglong2* wr = reinterpret_cast<const ulonglong2*>(&ws[(k4 * 4 + c) * D]);
#pragma unroll
                for (int j4 = 0; j4 < 16; j4++) {
                    ulonglong2 w = wr[j4];
                    fma2(acc[2 * j4],     a, w.x);
                    fma2(acc[2 * j4 + 1], a, w.y);
                }
            }
        }
        for (int k4 = 0; k4 < 16; k4++) {
            float4 av = ar[k4];
#pragma unroll
            for (int c = 0; c < 4; c++) {
                float xs = (c == 0) ? av.x : (c == 1) ? av.y : (c == 2) ? av.z : av.w;
                u64 a = pack2(xs, xs);
                const ulonglong2* wr = reinterpret_cast<const ulonglong2*>(&ws[(64 + k4 * 4 + c) * D]);
#pragma unroll
                for (int j4 = 0; j4 < 16; j4++) {
                    ulonglong2 w = wr[j4];
                    fma2(acc[2 * j4],     a, w.x);
                    fma2(acc[2 * j4 + 1], a, w.y);
                }
            }
        }

        float* o = x_dst + (size_t)v * D;
#pragma unroll
        for (int j = 0; j < 32; j++) {
            float lo, hi;
            unpack2(acc[j], lo, hi);
            float2 rv;
            rv.x = fmaxf(lo, 0.f);
            rv.y = fmaxf(hi, 0.f);
            *reinterpret_cast<float2*>(&o[2 * j]) = rv;
        }
    }
}

// ---------------- launcher ----------------
extern "C" void kernel_launch(void* const* d_in, const int* in_sizes, int n_in,
                              void* d_out, int out_size) {
    const float* x      = (const float*)d_in[0];
    const void*  eidx   = d_in[1];
    const float* eattr  = (const float*)d_in[2];
    const float* msg_w  = (const float*)d_in[3];
    const float* msg_b  = (const float*)d_in[4];
    const float* upd_w  = (const float*)d_in[5];
    const float* upd_b  = (const float*)d_in[6];

    const int N = in_sizes[0] / D;
    const int E = in_sizes[2] / EDGE_DIM;
    const int L = in_sizes[4] / D;

    detect_kernel<<<1, 256>>>((const unsigned int*)eidx);
    conv_idx_kernel<<<(E + 255) / 256, 256>>>(eidx, E);

    // Persistent node grids: one balanced wave over 148 SMs.
    int pers = (N + 255) / 256;
    if (pers > 148) pers = 148;
    const int edge_blocks = (E + 8 * EPW - 1) / (8 * EPW);

    for (int l = 0; l < L; l++) {
        const float* xin = (l == 0) ? x : nullptr;            // nullptr -> g_x
        float* xout = (l == L - 1) ? (float*)d_out : nullptr; // nullptr -> g_x

        dim3 pq_grid(pers, 2);
        pq_kernel<<<pq_grid, 256>>>(xin, msg_w, msg_b, l, N);
        edge_kernel<<<edge_blocks, 256>>>(eattr, msg_w, l, E);
        upd_kernel<<<pers, 256>>>(xin, upd_w, upd_b, l, N, xout);
    }
}